// round 4
// baseline (speedup 1.0000x reference)
#include <cuda_runtime.h>
#include <cstdint>

#define B_ 4
#define S_ 2048
#define E_ 1024
#define H_ 16
#define D_ 64
#define BS_ (B_*S_)
#define BHSD (B_*H_*S_*D_)

// Scratch (device globals — no allocations allowed)
__device__ __align__(16) float g_buf[3*(size_t)BHSD]; // Q|K|V rounded (Q pre-scaled)
__device__ __align__(16) float g_ctx[(size_t)BS_*H_*D_];
__device__ __align__(16) float g_xr[(size_t)BS_*E_];
__device__ __align__(16) float g_Wqr[H_*E_*D_];
__device__ __align__(16) float g_Wkr[H_*E_*D_];
__device__ __align__(16) float g_Wvr[H_*E_*D_];
__device__ __align__(16) float g_Wor[H_*D_*E_];

#define LOG2E 1.4426950408889634f

// ---------------------------------------------------------------------------
__device__ __forceinline__ float f2tff(float f) {
    unsigned u; asm("cvt.rna.tf32.f32 %0, %1;" : "=r"(u) : "f"(f));
    return __uint_as_float(u);
}
__device__ __forceinline__ void mma8(float* c, const unsigned* a, const unsigned* b) {
    asm volatile(
        "mma.sync.aligned.m16n8k8.row.col.f32.tf32.tf32.f32 "
        "{%0,%1,%2,%3}, {%4,%5,%6,%7}, {%8,%9}, {%0,%1,%2,%3};\n"
        : "+f"(c[0]), "+f"(c[1]), "+f"(c[2]), "+f"(c[3])
        : "r"(a[0]), "r"(a[1]), "r"(a[2]), "r"(a[3]), "r"(b[0]), "r"(b[1]));
}
__device__ __forceinline__ void cp16(uint32_t d, const float* s) {
    asm volatile("cp.async.cg.shared.global [%0], [%1], 16;\n" :: "r"(d), "l"(s));
}
__device__ __forceinline__ void cp_commit() { asm volatile("cp.async.commit_group;\n"); }
__device__ __forceinline__ void cp_wait0()  { asm volatile("cp.async.wait_group 0;\n" ::: "memory"); }

// ---------------------------------------------------------------------------
// prep: one launch, rounds all 5 arrays to tf32 (rna).
// segments (float4 units): x 2097152 | Wq 262144 | Wk 262144 | Wv 262144 | Wo 262144
// ---------------------------------------------------------------------------
#define N4_X  (BS_*E_/4)
#define N4_W  (H_*E_*D_/4)
#define N4_TOT (N4_X + 4*N4_W)

__global__ void prep_kernel(const float4* __restrict__ x,
                            const float4* __restrict__ Wq, const float4* __restrict__ Wk,
                            const float4* __restrict__ Wv, const float4* __restrict__ Wo)
{
    int i = blockIdx.x * blockDim.x + threadIdx.x;
    int stride = gridDim.x * blockDim.x;
    for (; i < N4_TOT; i += stride) {
        const float4* src; float4* dst; int j;
        if (i < N4_X)               { src = x;  dst = (float4*)g_xr;  j = i; }
        else if (i < N4_X + N4_W)   { src = Wq; dst = (float4*)g_Wqr; j = i - N4_X; }
        else if (i < N4_X + 2*N4_W) { src = Wk; dst = (float4*)g_Wkr; j = i - N4_X - N4_W; }
        else if (i < N4_X + 3*N4_W) { src = Wv; dst = (float4*)g_Wvr; j = i - N4_X - 2*N4_W; }
        else                        { src = Wo; dst = (float4*)g_Wor; j = i - N4_X - 3*N4_W; }
        float4 v = src[j];
        float4 w;
        w.x = f2tff(v.x); w.y = f2tff(v.y); w.z = f2tff(v.z); w.w = f2tff(v.w);
        dst[j] = w;
    }
}

// ---------------------------------------------------------------------------
// Kernel 1: fused QKV projection, tf32 mma, cp.async double-buffered.
// Block tile 128(M) x 128(N = two (w,h) outputs), K-tile 32, 256 thr / 8 warps.
// Q epilogue pre-scales by (1/8)*log2e for exp2-domain softmax.
// ---------------------------------------------------------------------------
#define GEMM_SMEM 71680

__global__ __launch_bounds__(256, 2) void qkv_kernel(
    const float* __restrict__ bq, const float* __restrict__ bk, const float* __restrict__ bv)
{
    extern __shared__ float sm[];
    const int tid  = threadIdx.x;
    const int m0   = blockIdx.x * 128;
    const int p0   = blockIdx.y * 2;
    const int lane = tid & 31, wid = tid >> 5;
    const int wm   = wid >> 1, wn = wid & 1;
    const int g    = lane >> 2, t = lane & 3;
    const uint32_t smb = (uint32_t)__cvta_generic_to_shared(sm);

    const float* aSrc[4]; uint32_t aDst[4];
    #pragma unroll
    for (int i = 0; i < 4; i++) {
        int lin = tid + i * 256, row = lin >> 3, c4 = lin & 7;
        aSrc[i] = g_xr + (size_t)(m0 + row) * E_ + c4 * 4;
        aDst[i] = smb + (uint32_t)(row * 36 + c4 * 4) * 4u;
    }
    const float* bSrc[4]; uint32_t bDst[4];
    #pragma unroll
    for (int i = 0; i < 4; i++) {
        int lin = tid + i * 256, row = lin >> 5, c4 = lin & 31, ncol = c4 * 4;
        int pb = p0 + (c4 >> 4), wv = pb >> 4, hh = pb & 15;
        const float* base = (wv == 0) ? g_Wqr : (wv == 1) ? g_Wkr : g_Wvr;
        bSrc[i] = base + (size_t)hh * E_ * D_ + row * D_ + (ncol & 63);
        bDst[i] = smb + (uint32_t)(9216 + row * 136 + ncol) * 4u;
    }

    #pragma unroll
    for (int i = 0; i < 4; i++) { cp16(aDst[i], aSrc[i]); cp16(bDst[i], bSrc[i]); }
    cp_commit();

    float c[2][8][4];
    #pragma unroll
    for (int mi = 0; mi < 2; mi++)
        #pragma unroll
        for (int f = 0; f < 8; f++)
            #pragma unroll
            for (int r = 0; r < 4; r++) c[mi][f][r] = 0.f;

    for (int kt = 0; kt < 32; kt++) {
        cp_wait0();
        __syncthreads();
        if (kt + 1 < 32) {
            const uint32_t st = ((kt + 1) & 1);
            #pragma unroll
            for (int i = 0; i < 4; i++) {
                cp16(aDst[i] + st * 18432u, aSrc[i] + (size_t)(kt + 1) * 32);
                cp16(bDst[i] + st * 17408u, bSrc[i] + (size_t)(kt + 1) * 32 * D_);
            }
            cp_commit();
        }
        const float* A  = sm + (kt & 1) * 4608;
        const float* Bt = sm + 9216 + (kt & 1) * 4352;

        #pragma unroll
        for (int ks = 0; ks < 4; ks++) {
            const int k8 = ks * 8;
            unsigned a[2][4];
            #pragma unroll
            for (int mi = 0; mi < 2; mi++) {
                int r = wm * 32 + mi * 16 + g;
                a[mi][0] = __float_as_uint(A[r * 36 + k8 + t]);
                a[mi][1] = __float_as_uint(A[(r + 8) * 36 + k8 + t]);
                a[mi][2] = __float_as_uint(A[r * 36 + k8 + t + 4]);
                a[mi][3] = __float_as_uint(A[(r + 8) * 36 + k8 + t + 4]);
            }
            #pragma unroll
            for (int f = 0; f < 8; f++) {
                unsigned b[2];
                const int nc = wn * 64 + f * 8 + g;
                b[0] = __float_as_uint(Bt[(k8 + t) * 136 + nc]);
                b[1] = __float_as_uint(Bt[(k8 + t + 4) * 136 + nc]);
                mma8(c[0][f], a[0], b);
                mma8(c[1][f], a[1], b);
            }
        }
    }

    // epilogue: bias + tf32-round (+0.125*log2e scale for Q) -> g_buf [B,H,S,D]
    const int p  = p0 + wn;
    const int wv = p >> 4, hh = p & 15;
    float* outb = g_buf + (size_t)wv * BHSD;
    const float* bb = ((wv == 0) ? bq : (wv == 1) ? bk : bv) + hh * D_;
    const float scl = (wv == 0) ? (0.125f * LOG2E) : 1.0f;

    #pragma unroll
    for (int mi = 0; mi < 2; mi++) {
        const int r0 = m0 + wm * 32 + mi * 16 + g;
        #pragma unroll
        for (int f = 0; f < 8; f++) {
            const int col = f * 8 + t * 2;
            const float b0v = bb[col], b1v = bb[col + 1];
            {
                int gr = r0;
                float2 v;
                v.x = f2tff((c[mi][f][0] + b0v) * scl);
                v.y = f2tff((c[mi][f][1] + b1v) * scl);
                *(float2*)(outb + (((size_t)(gr >> 11) * H_ + hh) * S_ + (gr & 2047)) * D_ + col) = v;
            }
            {
                int gr = r0 + 8;
                float2 v;
                v.x = f2tff((c[mi][f][2] + b0v) * scl);
                v.y = f2tff((c[mi][f][3] + b1v) * scl);
                *(float2*)(outb + (((size_t)(gr >> 11) * H_ + hh) * S_ + (gr & 2047)) * D_ + col) = v;
            }
        }
    }
}

// ---------------------------------------------------------------------------
// Kernel 2: causal flash attention, tf32 mma, deferred-O pipeline.
// Per KV tile: S-mma(jt) -> O-mma(jt-1) -> sync -> prefetch(jt+1) -> softmax(jt).
// Softmax (exp2-domain) overlaps the next tile's cp.async wait.
// Heavy blocks (large iq) scheduled first.
// ---------------------------------------------------------------------------
#define FLASH_SMEM 106496

__global__ __launch_bounds__(256, 2) void flash_kernel()
{
    extern __shared__ float sm[];
    float* Ps = sm + 17920;

    const int iq = (int)(gridDim.x - 1 - blockIdx.x);   // heavy-first
    const int h = blockIdx.y, b = blockIdx.z;
    const int q0 = iq * 128;
    const size_t head_base = ((size_t)b * H_ + h) * S_ * D_;
    const float* Qg = g_buf + head_base;          // pre-scaled (0.125*log2e), rounded
    const float* Kg = g_buf + BHSD + head_base;   // rounded

    const int tid  = threadIdx.x;
    const int lane = tid & 31, wid = tid >> 5;
    const int g    = lane >> 2, t = lane & 3;
    const int qrow = wid * 16 + g;
    const uint32_t smb = (uint32_t)__cvta_generic_to_shared(sm);

    const float* kSrc[4]; uint32_t kDst[4], vDst[4];
    #pragma unroll
    for (int i = 0; i < 4; i++) {
        int lin = tid + i * 256, row = lin >> 4, c4 = lin & 15;
        kSrc[i] = Kg + (size_t)row * D_ + c4 * 4;
        kDst[i] = smb + (uint32_t)(row * 68 + c4 * 4) * 4u;
        vDst[i] = smb + (uint32_t)(8704 + row * 72 + c4 * 4) * 4u;
    }

    // prefetch K/V tile 0 -> stage 0
    #pragma unroll
    for (int i = 0; i < 4; i++) { cp16(kDst[i], kSrc[i]); cp16(vDst[i], kSrc[i] + BHSD); }
    cp_commit();

    // stage Q into Ps (one-time), lift warp-private A-fragments to regs
    #pragma unroll
    for (int i = 0; i < 8; i++) {
        int lin = tid + i * 256, row = lin >> 4, c4 = lin & 15;
        *(float4*)&Ps[row * 68 + c4 * 4] =
            *(const float4*)(Qg + (size_t)(q0 + row) * D_ + c4 * 4);
    }
    __syncthreads();

    unsigned aQ[8][4];
    #pragma unroll
    for (int kk = 0; kk < 8; kk++) {
        const int d8 = kk * 8;
        aQ[kk][0] = __float_as_uint(Ps[qrow * 68 + d8 + t]);
        aQ[kk][1] = __float_as_uint(Ps[(qrow + 8) * 68 + d8 + t]);
        aQ[kk][2] = __float_as_uint(Ps[qrow * 68 + d8 + t + 4]);
        aQ[kk][3] = __float_as_uint(Ps[(qrow + 8) * 68 + d8 + t + 4]);
    }
    __syncthreads();   // Q frags read before Ps reused for P

    float cO[8][4];
    #pragma unroll
    for (int f = 0; f < 8; f++)
        #pragma unroll
        for (int r = 0; r < 4; r++) cO[f][r] = 0.f;
    float m0_ = -1e30f, m1_ = -1e30f, l0_ = 0.f, l1_ = 0.f;

    const int jtmax = 2 * iq + 1;
    for (int jt = 0; jt <= jtmax; jt++) {
        cp_wait0();
        __syncthreads();                       // tile jt resident in stage jt&1
        const float* Kst = sm + (jt & 1) * 4352;
        const int k0 = jt * 64;

        // --- S-mma(jt) ---
        float cS[8][4];
        #pragma unroll
        for (int f = 0; f < 8; f++)
            #pragma unroll
            for (int r = 0; r < 4; r++) cS[f][r] = 0.f;
        #pragma unroll
        for (int kk = 0; kk < 8; kk++) {
            const int d8 = kk * 8;
            #pragma unroll
            for (int f = 0; f < 8; f++) {
                unsigned bfr[2];
                bfr[0] = __float_as_uint(Kst[(f * 8 + g) * 68 + d8 + t]);
                bfr[1] = __float_as_uint(Kst[(f * 8 + g) * 68 + d8 + t + 4]);
                mma8(cS[f], aQ[kk], bfr);
            }
        }

        // --- O-mma(jt-1): consumes Ps (P of prev tile) and V stage (jt-1)&1 ---
        if (jt > 0) {
            const float* Vprev = sm + 8704 + ((jt - 1) & 1) * 4608;
            #pragma unroll
            for (int kk = 0; kk < 8; kk++) {
                const int s8 = kk * 8;
                unsigned a[4];
                a[0] = __float_as_uint(Ps[qrow * 68 + s8 + t]);
                a[1] = __float_as_uint(Ps[(qrow + 8) * 68 + s8 + t]);
                a[2] = __float_as_uint(Ps[qrow * 68 + s8 + t + 4]);
                a[3] = __float_as_uint(Ps[(qrow + 8) * 68 + s8 + t + 4]);
                #pragma unroll
                for (int f = 0; f < 8; f++) {
                    unsigned bfr[2];
                    bfr[0] = __float_as_uint(Vprev[(s8 + t) * 72 + f * 8 + g]);
                    bfr[1] = __float_as_uint(Vprev[(s8 + t + 4) * 72 + f * 8 + g]);
                    mma8(cO[f], a, bfr);
                }
            }
        }
        __syncthreads();                       // all reads of stage (jt-1)&1 done

        // --- prefetch tile jt+1 into stage (jt+1)&1 ---
        if (jt < jtmax) {
            const uint32_t st = ((jt + 1) & 1);
            #pragma unroll
            for (int i = 0; i < 4; i++) {
                cp16(kDst[i] + st * 17408u, kSrc[i] + (size_t)(jt + 1) * 4096);
                cp16(vDst[i] + st * 18432u, kSrc[i] + BHSD + (size_t)(jt + 1) * 4096);
            }
            cp_commit();
        }

        // --- mask + softmax(jt), exp2 domain; overlaps the prefetch ---
        if (jt >= 2 * iq) {
            const int r0 = q0 + qrow, r1 = r0 + 8;
            #pragma unroll
            for (int f = 0; f < 8; f++) {
                const int col = k0 + f * 8 + t * 2;
                if (col     > r0) cS[f][0] = -1e30f;
                if (col + 1 > r0) cS[f][1] = -1e30f;
                if (col     > r1) cS[f][2] = -1e30f;
                if (col + 1 > r1) cS[f][3] = -1e30f;
            }
        }

        float rm0 = -1e30f, rm1 = -1e30f;
        #pragma unroll
        for (int f = 0; f < 8; f++) {
            rm0 = fmaxf(rm0, fmaxf(cS[f][0], cS[f][1]));
            rm1 = fmaxf(rm1, fmaxf(cS[f][2], cS[f][3]));
        }
        rm0 = fmaxf(rm0, __shfl_xor_sync(0xffffffffu, rm0, 1));
        rm0 = fmaxf(rm0, __shfl_xor_sync(0xffffffffu, rm0, 2));
        rm1 = fmaxf(rm1, __shfl_xor_sync(0xffffffffu, rm1, 1));
        rm1 = fmaxf(rm1, __shfl_xor_sync(0xffffffffu, rm1, 2));

        const float nm0 = fmaxf(m0_, rm0);
        const float nm1 = fmaxf(m1_, rm1);
        const float corr0 = exp2f(m0_ - nm0);
        const float corr1 = exp2f(m1_ - nm1);
        m0_ = nm0; m1_ = nm1;

        float rs0 = 0.f, rs1 = 0.f;
        #pragma unroll
        for (int f = 0; f < 8; f++) {
            float p0v = exp2f(cS[f][0] - nm0);
            float p1v = exp2f(cS[f][1] - nm0);
            float p2v = exp2f(cS[f][2] - nm1);
            float p3v = exp2f(cS[f][3] - nm1);
            rs0 += p0v + p1v;
            rs1 += p2v + p3v;
            float2 v0; v0.x = f2tff(p0v); v0.y = f2tff(p1v);
            *(float2*)&Ps[qrow * 68 + f * 8 + t * 2] = v0;
            float2 v1; v1.x = f2tff(p2v); v1.y = f2tff(p3v);
            *(float2*)&Ps[(qrow + 8) * 68 + f * 8 + t * 2] = v1;
        }
        rs0 += __shfl_xor_sync(0xffffffffu, rs0, 1);
        rs0 += __shfl_xor_sync(0xffffffffu, rs0, 2);
        rs1 += __shfl_xor_sync(0xffffffffu, rs1, 1);
        rs1 += __shfl_xor_sync(0xffffffffu, rs1, 2);
        l0_ = l0_ * corr0 + rs0;
        l1_ = l1_ * corr1 + rs1;
        #pragma unroll
        for (int f = 0; f < 8; f++) {
            cO[f][0] *= corr0; cO[f][1] *= corr0;
            cO[f][2] *= corr1; cO[f][3] *= corr1;
        }
        __syncwarp();
    }

    // --- final O-mma(jtmax) ---
    {
        const float* Vlast = sm + 8704 + (jtmax & 1) * 4608;
        #pragma unroll
        for (int kk = 0; kk < 8; kk++) {
            const int s8 = kk * 8;
            unsigned a[4];
            a[0] = __float_as_uint(Ps[qrow * 68 + s8 + t]);
            a[1] = __float_as_uint(Ps[(qrow + 8) * 68 + s8 + t]);
            a[2] = __float_as_uint(Ps[qrow * 68 + s8 + t + 4]);
            a[3] = __float_as_uint(Ps[(qrow + 8) * 68 + s8 + t + 4]);
            #pragma unroll
            for (int f = 0; f < 8; f++) {
                unsigned bfr[2];
                bfr[0] = __float_as_uint(Vlast[(s8 + t) * 72 + f * 8 + g]);
                bfr[1] = __float_as_uint(Vlast[(s8 + t + 4) * 72 + f * 8 + g]);
                mma8(cO[f], a, bfr);
            }
        }
    }

    // epilogue: normalize, round (oproj A operand), write ctx [B,S,H,D]
    const float inv0 = 1.0f / l0_;
    const float inv1 = 1.0f / l1_;
    const int q_a = q0 + qrow, q_b = q_a + 8;
    #pragma unroll
    for (int f = 0; f < 8; f++) {
        const int col = f * 8 + t * 2;
        float2 v0; v0.x = f2tff(cO[f][0] * inv0); v0.y = f2tff(cO[f][1] * inv0);
        *(float2*)(g_ctx + (((size_t)b * S_ + q_a) * H_ + h) * D_ + col) = v0;
        float2 v1; v1.x = f2tff(cO[f][2] * inv1); v1.y = f2tff(cO[f][3] * inv1);
        *(float2*)(g_ctx + (((size_t)b * S_ + q_b) * H_ + h) * D_ + col) = v1;
    }
}

// ---------------------------------------------------------------------------
// Kernel 3: output projection, same skeleton as qkv. grid (64, 8).
// ---------------------------------------------------------------------------
__global__ __launch_bounds__(256, 2) void oproj_kernel(
    const float* __restrict__ bo, float* __restrict__ out)
{
    extern __shared__ float sm[];
    const int tid  = threadIdx.x;
    const int m0   = blockIdx.x * 128;
    const int n0   = blockIdx.y * 128;
    const int lane = tid & 31, wid = tid >> 5;
    const int wm   = wid >> 1, wn = wid & 1;
    const int g    = lane >> 2, t = lane & 3;
    const uint32_t smb = (uint32_t)__cvta_generic_to_shared(sm);

    const float* aSrc[4]; uint32_t aDst[4];
    #pragma unroll
    for (int i = 0; i < 4; i++) {
        int lin = tid + i * 256, row = lin >> 3, c4 = lin & 7;
        aSrc[i] = g_ctx + (size_t)(m0 + row) * E_ + c4 * 4;
        aDst[i] = smb + (uint32_t)(row * 36 + c4 * 4) * 4u;
    }
    const float* bSrc[4]; uint32_t bDst[4];
    #pragma unroll
    for (int i = 0; i < 4; i++) {
        int lin = tid + i * 256, row = lin >> 5, c4 = lin & 31, ncol = c4 * 4;
        bSrc[i] = g_Wor + (size_t)row * E_ + n0 + ncol;
        bDst[i] = smb + (uint32_t)(9216 + row * 136 + ncol) * 4u;
    }

    #pragma unroll
    for (int i = 0; i < 4; i++) { cp16(aDst[i], aSrc[i]); cp16(bDst[i], bSrc[i]); }
    cp_commit();

    float c[2][8][4];
    #pragma unroll
    for (int mi = 0; mi < 2; mi++)
        #pragma unroll
        for (int f = 0; f < 8; f++)
            #pragma unroll
            for (int r = 0; r < 4; r++) c[mi][f][r] = 0.f;

    for (int kt = 0; kt < 32; kt++) {
        cp_wait0();
        __syncthreads();
        if (kt + 1 < 32) {
            const uint32_t st = ((kt + 1) & 1);
            #pragma unroll
            for (int i = 0; i < 4; i++) {
                cp16(aDst[i] + st * 18432u, aSrc[i] + (size_t)(kt + 1) * 32);
                cp16(bDst[i] + st * 17408u, bSrc[i] + (size_t)(kt + 1) * 32 * E_);
            }
            cp_commit();
        }
        const float* A  = sm + (kt & 1) * 4608;
        const float* Bt = sm + 9216 + (kt & 1) * 4352;

        #pragma unroll
        for (int ks = 0; ks < 4; ks++) {
            const int k8 = ks * 8;
            unsigned a[2][4];
            #pragma unroll
            for (int mi = 0; mi < 2; mi++) {
                int r = wm * 32 + mi * 16 + g;
                a[mi][0] = __float_as_uint(A[r * 36 + k8 + t]);
                a[mi][1] = __float_as_uint(A[(r + 8) * 36 + k8 + t]);
                a[mi][2] = __float_as_uint(A[r * 36 + k8 + t + 4]);
                a[mi][3] = __float_as_uint(A[(r + 8) * 36 + k8 + t + 4]);
            }
            #pragma unroll
            for (int f = 0; f < 8; f++) {
                unsigned b[2];
                const int nc = wn * 64 + f * 8 + g;
                b[0] = __float_as_uint(Bt[(k8 + t) * 136 + nc]);
                b[1] = __float_as_uint(Bt[(k8 + t + 4) * 136 + nc]);
                mma8(c[0][f], a[0], b);
                mma8(c[1][f], a[1], b);
            }
        }
    }

    #pragma unroll
    for (int mi = 0; mi < 2; mi++) {
        const int r0 = m0 + wm * 32 + mi * 16 + g;
        #pragma unroll
        for (int f = 0; f < 8; f++) {
            const int col = n0 + wn * 64 + f * 8 + t * 2;
            const float b0v = bo[col], b1v = bo[col + 1];
            float2 v0; v0.x = c[mi][f][0] + b0v; v0.y = c[mi][f][1] + b1v;
            *(float2*)(out + (size_t)r0 * E_ + col) = v0;
            float2 v1; v1.x = c[mi][f][2] + b0v; v1.y = c[mi][f][3] + b1v;
            *(float2*)(out + (size_t)(r0 + 8) * E_ + col) = v1;
        }
    }
}

// ---------------------------------------------------------------------------
extern "C" void kernel_launch(void* const* d_in, const int* in_sizes, int n_in,
                              void* d_out, int out_size)
{
    const float* x  = (const float*)d_in[0];
    const float* Wq = (const float*)d_in[1];
    const float* Wk = (const float*)d_in[2];
    const float* Wv = (const float*)d_in[3];
    const float* bq = (const float*)d_in[4];
    const float* bk = (const float*)d_in[5];
    const float* bv = (const float*)d_in[6];
    const float* Wo = (const float*)d_in[7];
    const float* bo = (const float*)d_in[8];
    float* out = (float*)d_out;

    cudaFuncSetAttribute(qkv_kernel,  cudaFuncAttributeMaxDynamicSharedMemorySize, GEMM_SMEM);
    cudaFuncSetAttribute(flash_kernel, cudaFuncAttributeMaxDynamicSharedMemorySize, FLASH_SMEM);
    cudaFuncSetAttribute(oproj_kernel, cudaFuncAttributeMaxDynamicSharedMemorySize, GEMM_SMEM);

    prep_kernel<<<2368, 256>>>((const float4*)x, (const float4*)Wq,
                               (const float4*)Wk, (const float4*)Wv, (const float4*)Wo);
    qkv_kernel<<<dim3(BS_ / 128, 24), 256, GEMM_SMEM>>>(bq, bk, bv);
    flash_kernel<<<dim3(S_ / 128, H_, B_), 256, FLASH_SMEM>>>();
    oproj_kernel<<<dim3(BS_ / 128, E_ / 128), 256, GEMM_SMEM>>>(bo, out);
}